// round 1
// baseline (speedup 1.0000x reference)
#include <cuda_runtime.h>
#include <cuda_bf16.h>

// Shared gate parameters, precomputed once per launch by a tiny kernel.
__device__ float2 g_e[12];  // e^{i*theta/2} = (cos, sin)
__device__ float2 g_p[3];   // e^{i*phi}     = (cos, sin)

__global__ void precompute_k(const float* __restrict__ thetas,
                             const float* __restrict__ phis) {
    int t = threadIdx.x;
    if (t < 12) {
        float s, c;
        __sincosf(0.5f * thetas[t], &s, &c);
        g_e[t] = make_float2(c, s);
    } else if (t < 15) {
        float s, c;
        __sincosf(phis[t - 12], &s, &c);
        g_p[t - 12] = make_float2(c, s);
    }
}

// RX(theta) on the wire with bit-mask TB, over the first N amplitudes.
// Gate = [[c, -i s],[-i s, c]], c=cos(t/2), s=sin(t/2).
template <int N, int TB>
__device__ __forceinline__ void rx_g(float (&sr)[32], float (&si)[32],
                                     float c, float s) {
#pragma unroll
    for (int i = 0; i < N; i++) {
        if (i & TB) continue;
        const int j = i | TB;
        float a0r = sr[i], a0i = si[i], a1r = sr[j], a1i = si[j];
        sr[i] = c * a0r + s * a1i;
        si[i] = c * a0i - s * a1r;
        sr[j] = c * a1r + s * a0i;
        si[j] = c * a1i - s * a0r;
    }
}

// Controlled-X_theta: when ctrl bit CB = 1, apply
// [[0, -i e],[ -i conj(e), 0]] on target bit TB, e = (er, ei) = e^{i theta/2}.
template <int N, int CB, int TB>
__device__ __forceinline__ void cu_g(float (&sr)[32], float (&si)[32],
                                     float er, float ei) {
#pragma unroll
    for (int i = 0; i < N; i++) {
        if (!(i & CB) || (i & TB)) continue;
        const int j = i | TB;
        float t0r = sr[i], t0i = si[i], t1r = sr[j], t1i = si[j];
        // t0' = (-i e) * t1 = (ei, -er) * t1
        sr[i] = ei * t1r + er * t1i;
        si[i] = ei * t1i - er * t1r;
        // t1' = (-i conj(e)) * t0 = (-ei, -er) * t0
        sr[j] = er * t0i - ei * t0r;
        si[j] = -(ei * t0i + er * t0r);
    }
}

// One full layer on the 32-dim state (wire1..4 masks: 8,4,2,1; wire0 = bit 4).
template <int L>
__device__ __forceinline__ void layer32(float (&sr)[32], float (&si)[32],
                                        const float (&pc)[12],
                                        const float (&ps)[12]) {
    rx_g<32, 8>(sr, si, pc[4 * L + 0], ps[4 * L + 0]);
    rx_g<32, 4>(sr, si, pc[4 * L + 1], ps[4 * L + 1]);
    rx_g<32, 2>(sr, si, pc[4 * L + 2], ps[4 * L + 2]);
    rx_g<32, 1>(sr, si, pc[4 * L + 3], ps[4 * L + 3]);
    float2 e;
    e = g_e[4 * L + 0]; cu_g<32, 8, 4>(sr, si, e.x, e.y);
    e = g_e[4 * L + 1]; cu_g<32, 4, 2>(sr, si, e.x, e.y);
    e = g_e[4 * L + 2]; cu_g<32, 2, 1>(sr, si, e.x, e.y);
    e = g_e[4 * L + 3]; cu_g<32, 1, 8>(sr, si, e.x, e.y);
    // CPhase(phi_L) on wires 0,1: indices with bit4 and bit3 set -> 24..31
    float2 ph = g_p[L];
#pragma unroll
    for (int j = 24; j < 32; j++) {
        float r = sr[j], m = si[j];
        sr[j] = ph.x * r - ph.y * m;
        si[j] = ph.x * m + ph.y * r;
    }
}

__global__ void __launch_bounds__(128)
sim_k(const float* __restrict__ x, float* __restrict__ out) {
    int p = blockIdx.x * 128 + threadIdx.x;
    int b = p >> 14;
    int rem = p & 16383;
    int h2 = rem >> 7;
    int w2 = rem & 127;
    const float* xb = x + (size_t)b * 196608 + (size_t)h2 * 512 + (size_t)w2 * 2;

    // Per-patch RX half-angle sin/cos. pix index = ch*4 + dy*2 + dx.
    float pcv[12], psv[12];
#pragma unroll
    for (int ch = 0; ch < 3; ch++) {
#pragma unroll
        for (int dy = 0; dy < 2; dy++) {
            float2 v = *reinterpret_cast<const float2*>(xb + ch * 65536 + dy * 256);
            int k = ch * 4 + dy * 2;
            __sincosf(0.5f * v.x, &psv[k], &pcv[k]);
            __sincosf(0.5f * v.y, &psv[k + 1], &pcv[k + 1]);
        }
    }

    // State: index = a<<4 | b<<3 | c<<2 | d<<1 | e (wires 0..4).
    // Wire 0 is untouched until the first CPhase, so layer 0 runs on the
    // 16-dim (b,c,d,e) subspace; both H branches are identical until then.
    // The two H's + Z-measure fold into ev = sum_j Re(psi_j * conj(psi'_j)).
    float sr[32], si[32];
#pragma unroll
    for (int i = 0; i < 16; i++) { sr[i] = 0.f; si[i] = 0.f; }
    sr[0] = 1.f;

    // Layer 0 on 16-dim subspace
    rx_g<16, 8>(sr, si, pcv[0], psv[0]);
    rx_g<16, 4>(sr, si, pcv[1], psv[1]);
    rx_g<16, 2>(sr, si, pcv[2], psv[2]);
    rx_g<16, 1>(sr, si, pcv[3], psv[3]);
    float2 e;
    e = g_e[0]; cu_g<16, 8, 4>(sr, si, e.x, e.y);
    e = g_e[1]; cu_g<16, 4, 2>(sr, si, e.x, e.y);
    e = g_e[2]; cu_g<16, 2, 1>(sr, si, e.x, e.y);
    e = g_e[3]; cu_g<16, 1, 8>(sr, si, e.x, e.y);

    // Fork branches: a=1 branch gets CPhase(phi_0) on its b=1 amplitudes.
    float2 ph = g_p[0];
#pragma unroll
    for (int j = 0; j < 16; j++) {
        if (j & 8) {
            sr[16 + j] = ph.x * sr[j] - ph.y * si[j];
            si[16 + j] = ph.x * si[j] + ph.y * sr[j];
        } else {
            sr[16 + j] = sr[j];
            si[16 + j] = si[j];
        }
    }

    layer32<1>(sr, si, pcv, psv);
    layer32<2>(sr, si, pcv, psv);

    float ev = 0.f;
#pragma unroll
    for (int j = 0; j < 16; j++)
        ev += sr[j] * sr[j + 16] + si[j] * si[j + 16];
    out[p] = ev;
}

extern "C" void kernel_launch(void* const* d_in, const int* in_sizes, int n_in,
                              void* d_out, int out_size) {
    const float* x = nullptr;
    const float* thetas = nullptr;
    const float* phis = nullptr;
    for (int i = 0; i < n_in; i++) {
        if (in_sizes[i] == 12) thetas = (const float*)d_in[i];
        else if (in_sizes[i] == 3) phis = (const float*)d_in[i];
        else x = (const float*)d_in[i];
    }
    float* out = (float*)d_out;

    precompute_k<<<1, 32>>>(thetas, phis);
    sim_k<<<out_size / 128, 128>>>(x, out);
}

// round 2
// speedup vs baseline: 1.0399x; 1.0399x over previous
#include <cuda_runtime.h>
#include <cuda_bf16.h>

typedef unsigned long long u64;

// Shared gate parameters, precomputed once per launch by a tiny kernel.
__device__ float2 g_e[12];  // e^{i*theta/2} = (cos, sin)
__device__ float2 g_p[3];   // e^{i*phi}     = (cos, sin)

__global__ void precompute_k(const float* __restrict__ thetas,
                             const float* __restrict__ phis) {
    int t = threadIdx.x;
    if (t < 12) {
        float s, c;
        __sincosf(0.5f * thetas[t], &s, &c);
        g_e[t] = make_float2(c, s);
    } else if (t < 15) {
        float s, c;
        __sincosf(phis[t - 12], &s, &c);
        g_p[t - 12] = make_float2(c, s);
    }
}

// ---- packed f32x2 helpers (Blackwell FFMA2 path, PTX-only) ----
__device__ __forceinline__ u64 f2pk(float lo, float hi) {
    u64 r;
    asm("mov.b64 %0, {%1, %2};" : "=l"(r) : "f"(lo), "f"(hi));
    return r;
}
__device__ __forceinline__ void f2un(float& lo, float& hi, u64 v) {
    asm("mov.b64 {%0, %1}, %2;" : "=f"(lo), "=f"(hi) : "l"(v));
}
__device__ __forceinline__ u64 fma2(u64 a, u64 b, u64 c) {
    u64 r;
    asm("fma.rn.f32x2 %0, %1, %2, %3;" : "=l"(r) : "l"(a), "l"(b), "l"(c));
    return r;
}
__device__ __forceinline__ u64 mul2(u64 a, u64 b) {
    u64 r;
    asm("mul.rn.f32x2 %0, %1, %2;" : "=l"(r) : "l"(a), "l"(b));
    return r;
}

// State: 16 packed complex amplitudes. Packed lane = wire0 (bit 16 of the
// full 32-dim index): lo = a=0 branch, hi = a=1 branch. Wire0 is never a
// 2x2-gate target, so every RX/CU acts identically on both lanes.
// Index k = b<<3 | c<<2 | d<<1 | e (wires 1..4).

// RX(theta) on target bit TB: [[c, -is],[-is, c]].
template <int TB>
__device__ __forceinline__ void rx_p(u64 (&vr)[16], u64 (&vi)[16],
                                     float c, float s) {
    const u64 c2 = f2pk(c, c), s2 = f2pk(s, s), n2 = f2pk(-s, -s);
#pragma unroll
    for (int k = 0; k < 16; k++) {
        if (k & TB) continue;
        const int j = k | TB;
        u64 r0 = vr[k], i0 = vi[k], r1 = vr[j], i1 = vi[j];
        vr[k] = fma2(c2, r0, mul2(s2, i1));
        vi[k] = fma2(c2, i0, mul2(n2, r1));
        vr[j] = fma2(c2, r1, mul2(s2, i0));
        vi[j] = fma2(c2, i1, mul2(n2, r0));
    }
}

// Controlled X_theta: when ctrl bit CB=1 apply [[0,-ie],[-i conj(e),0]] on TB.
template <int CB, int TB>
__device__ __forceinline__ void cu_p(u64 (&vr)[16], u64 (&vi)[16],
                                     float er, float ei) {
    const u64 er2 = f2pk(er, er), ei2 = f2pk(ei, ei);
    const u64 ner2 = f2pk(-er, -er), nei2 = f2pk(-ei, -ei);
#pragma unroll
    for (int k = 0; k < 16; k++) {
        if (!(k & CB) || (k & TB)) continue;
        const int j = k | TB;
        u64 t0r = vr[k], t0i = vi[k], t1r = vr[j], t1i = vi[j];
        // t0' = (-i e) t1 = (ei, -er) * t1
        vr[k] = fma2(ei2, t1r, mul2(er2, t1i));
        vi[k] = fma2(ei2, t1i, mul2(ner2, t1r));
        // t1' = (-i conj(e)) t0 = (-ei, -er) * t0
        vr[j] = fma2(er2, t0i, mul2(nei2, t0r));
        vi[j] = fma2(nei2, t0i, mul2(ner2, t0r));
    }
}

// CPhase(phi) on wires (0,1): multiply hi lane of k=8..15 by e^{i phi}.
__device__ __forceinline__ void cph_p(u64 (&vr)[16], u64 (&vi)[16],
                                      float pc, float ps) {
    const u64 A = f2pk(1.0f, pc), Bn = f2pk(0.0f, -ps), Bp = f2pk(0.0f, ps);
#pragma unroll
    for (int k = 8; k < 16; k++) {
        u64 r = vr[k], i = vi[k];
        vr[k] = fma2(Bn, i, mul2(A, r));
        vi[k] = fma2(Bp, r, mul2(A, i));
    }
}

__global__ void __launch_bounds__(128, 4)
sim_k(const float* __restrict__ x, float* __restrict__ out) {
    int p = blockIdx.x * 128 + threadIdx.x;
    int b = p >> 14;
    int rem = p & 16383;
    int h2 = rem >> 7;
    int w2 = rem & 127;
    const float* xb = x + (size_t)b * 196608 + (size_t)h2 * 512 + (size_t)w2 * 2;

    // Per-patch RX half-angle sin/cos. pix index = ch*4 + dy*2 + dx.
    float pcv[12], psv[12];
#pragma unroll
    for (int ch = 0; ch < 3; ch++) {
#pragma unroll
        for (int dy = 0; dy < 2; dy++) {
            float2 v = *reinterpret_cast<const float2*>(xb + ch * 65536 + dy * 256);
            int k = ch * 4 + dy * 2;
            __sincosf(0.5f * v.x, &psv[k], &pcv[k]);
            __sincosf(0.5f * v.y, &psv[k + 1], &pcv[k + 1]);
        }
    }

    // Both H branches start at amp[0]=1 (normalization + both H's + Z-measure
    // fold into ev = sum_k Re(psi_lo psi_hi^*)).
    u64 vr[16], vi[16];
#pragma unroll
    for (int k = 0; k < 16; k++) { vr[k] = 0ull; vi[k] = 0ull; }
    vr[0] = f2pk(1.0f, 1.0f);

#pragma unroll
    for (int L = 0; L < 3; L++) {
        rx_p<8>(vr, vi, pcv[4 * L + 0], psv[4 * L + 0]);
        rx_p<4>(vr, vi, pcv[4 * L + 1], psv[4 * L + 1]);
        rx_p<2>(vr, vi, pcv[4 * L + 2], psv[4 * L + 2]);
        rx_p<1>(vr, vi, pcv[4 * L + 3], psv[4 * L + 3]);
        float2 e;
        e = g_e[4 * L + 0]; cu_p<8, 4>(vr, vi, e.x, e.y);
        e = g_e[4 * L + 1]; cu_p<4, 2>(vr, vi, e.x, e.y);
        e = g_e[4 * L + 2]; cu_p<2, 1>(vr, vi, e.x, e.y);
        e = g_e[4 * L + 3]; cu_p<1, 8>(vr, vi, e.x, e.y);
        float2 ph = g_p[L];
        cph_p(vr, vi, ph.x, ph.y);
    }

    float ev = 0.f;
#pragma unroll
    for (int k = 0; k < 16; k++) {
        float rl, rh, il, ih;
        f2un(rl, rh, vr[k]);
        f2un(il, ih, vi[k]);
        ev = fmaf(rl, rh, ev);
        ev = fmaf(il, ih, ev);
    }
    out[p] = ev;
}

extern "C" void kernel_launch(void* const* d_in, const int* in_sizes, int n_in,
                              void* d_out, int out_size) {
    const float* x = nullptr;
    const float* thetas = nullptr;
    const float* phis = nullptr;
    for (int i = 0; i < n_in; i++) {
        if (in_sizes[i] == 12) thetas = (const float*)d_in[i];
        else if (in_sizes[i] == 3) phis = (const float*)d_in[i];
        else x = (const float*)d_in[i];
    }
    float* out = (float*)d_out;

    precompute_k<<<1, 32>>>(thetas, phis);
    sim_k<<<out_size / 128, 128>>>(x, out);
}

// round 3
// speedup vs baseline: 1.0515x; 1.0111x over previous
#include <cuda_runtime.h>
#include <cuda_bf16.h>

// ---------------- scalar gate helpers ----------------

// RX(theta) on target bit TB over first N amplitudes.
// Gate = [[c, -is],[-is, c]].
template <int N, int TB>
__device__ __forceinline__ void rx_g(float (&sr)[32], float (&si)[32],
                                     float c, float s) {
#pragma unroll
    for (int i = 0; i < N; i++) {
        if (i & TB) continue;
        const int j = i | TB;
        float a0r = sr[i], a0i = si[i], a1r = sr[j], a1i = si[j];
        sr[i] = fmaf(c, a0r, s * a1i);
        si[i] = fmaf(c, a0i, -s * a1r);
        sr[j] = fmaf(c, a1r, s * a0i);
        si[j] = fmaf(c, a1i, -s * a0r);
    }
}

// Controlled X_theta: ctrl bit CB=1 -> [[0,-ie],[-i conj(e),0]] on TB,
// e = (er, ei) = e^{i theta/2}.
template <int N, int CB, int TB>
__device__ __forceinline__ void cu_g(float (&sr)[32], float (&si)[32],
                                     float er, float ei) {
#pragma unroll
    for (int i = 0; i < N; i++) {
        if (!(i & CB) || (i & TB)) continue;
        const int j = i | TB;
        float t0r = sr[i], t0i = si[i], t1r = sr[j], t1i = si[j];
        // t0' = (-i e) * t1 = (ei, -er) * t1
        sr[i] = fmaf(ei, t1r, er * t1i);
        si[i] = fmaf(ei, t1i, -er * t1r);
        // t1' = (-i conj(e)) * t0 = (-ei, -er) * t0
        sr[j] = fmaf(er, t0i, -ei * t0r);
        si[j] = -fmaf(ei, t0i, er * t0r);
    }
}

// ---------------- main kernel ----------------
// Block = 608 threads (19 warps). State regs (~64) force regs >= 56, so only
// ONE block fits the 64K register file -> exactly 19 resident warps/SM.
// grid = 432 -> 2.92 waves -> ~97% wave utilization.

#define TPB 608

__global__ void __launch_bounds__(TPB, 1)
sim_k(const float* __restrict__ x, const float* __restrict__ thetas,
      const float* __restrict__ phis, float* __restrict__ out, int P) {
    __shared__ float2 sh_e[12];  // e^{i theta/2}
    __shared__ float2 sh_p[3];   // e^{i phi}

    int tid = threadIdx.x;
    if (tid < 12) {
        float s, c;
        __sincosf(0.5f * thetas[tid], &s, &c);
        sh_e[tid] = make_float2(c, s);
    } else if (tid < 15) {
        float s, c;
        __sincosf(phis[tid - 12], &s, &c);
        sh_p[tid - 12] = make_float2(c, s);
    }
    __syncthreads();

    int p = blockIdx.x * TPB + tid;
    if (p >= P) return;

    int b = p >> 14;
    int rem = p & 16383;
    int h2 = rem >> 7;
    int w2 = rem & 127;
    const float* xb = x + (size_t)b * 196608 + (size_t)h2 * 512 + (size_t)w2 * 2;

    // Per-patch RX half-angle sin/cos. pix index = ch*4 + dy*2 + dx.
    float pcv[12], psv[12];
#pragma unroll
    for (int ch = 0; ch < 3; ch++) {
#pragma unroll
        for (int dy = 0; dy < 2; dy++) {
            float2 v = *reinterpret_cast<const float2*>(xb + ch * 65536 + dy * 256);
            int k = ch * 4 + dy * 2;
            __sincosf(0.5f * v.x, &psv[k], &pcv[k]);
            __sincosf(0.5f * v.y, &psv[k + 1], &pcv[k + 1]);
        }
    }

    // State index = a<<4 | b<<3 | c<<2 | d<<1 | e (wires 0..4).
    // Wire0 untouched until first CPhase -> layer 0 on 16-dim subspace; the
    // two H branches are identical until the fork. H's + Z-measure fold into
    // ev = sum Re(psi_lo * conj(psi_hi)) (all normalizations cancel).
    float sr[32], si[32];

    // ---- Layer-0 RX block == tensor product of RX|0> states ----
    // amp(k) = prod_w q_w(bit) * (-i)^popcount(k), q(0)=c, q(1)=s (magnitudes).
    {
        float ab[4], de[4];
        ab[0] = pcv[0] * pcv[1]; ab[1] = pcv[0] * psv[1];
        ab[2] = psv[0] * pcv[1]; ab[3] = psv[0] * psv[1];
        de[0] = pcv[2] * pcv[3]; de[1] = pcv[2] * psv[3];
        de[2] = psv[2] * pcv[3]; de[3] = psv[2] * psv[3];
#pragma unroll
        for (int k = 0; k < 16; k++) {
            float m = ab[k >> 2] * de[k & 3];
            int pc = __popc(k) & 3;  // compile-time folded
            sr[k] = (pc == 0) ? m : (pc == 2) ? -m : 0.0f;
            si[k] = (pc == 1) ? -m : (pc == 3) ? m : 0.0f;
        }
    }

    // ---- Layer-0 CU gates on 16-dim subspace ----
    float2 e;
    e = sh_e[0]; cu_g<16, 8, 4>(sr, si, e.x, e.y);
    e = sh_e[1]; cu_g<16, 4, 2>(sr, si, e.x, e.y);
    e = sh_e[2]; cu_g<16, 2, 1>(sr, si, e.x, e.y);
    e = sh_e[3]; cu_g<16, 1, 8>(sr, si, e.x, e.y);

    // ---- Fork: a=1 branch gets CPhase(phi_0) on b=1 amplitudes ----
    {
        float2 ph = sh_p[0];
#pragma unroll
        for (int j = 0; j < 16; j++) {
            if (j & 8) {
                sr[16 + j] = fmaf(ph.x, sr[j], -ph.y * si[j]);
                si[16 + j] = fmaf(ph.x, si[j], ph.y * sr[j]);
            } else {
                sr[16 + j] = sr[j];
                si[16 + j] = si[j];
            }
        }
    }

    // ---- Layers 1, 2 on full 32-dim state ----
#pragma unroll
    for (int L = 1; L < 3; L++) {
        rx_g<32, 8>(sr, si, pcv[4 * L + 0], psv[4 * L + 0]);
        rx_g<32, 4>(sr, si, pcv[4 * L + 1], psv[4 * L + 1]);
        rx_g<32, 2>(sr, si, pcv[4 * L + 2], psv[4 * L + 2]);
        rx_g<32, 1>(sr, si, pcv[4 * L + 3], psv[4 * L + 3]);
        e = sh_e[4 * L + 0]; cu_g<32, 8, 4>(sr, si, e.x, e.y);
        e = sh_e[4 * L + 1]; cu_g<32, 4, 2>(sr, si, e.x, e.y);
        e = sh_e[4 * L + 2]; cu_g<32, 2, 1>(sr, si, e.x, e.y);
        e = sh_e[4 * L + 3]; cu_g<32, 1, 8>(sr, si, e.x, e.y);
        // CPhase(phi_L) on wires 0,1: bit4 & bit3 set -> indices 24..31
        float2 ph = sh_p[L];
#pragma unroll
        for (int j = 24; j < 32; j++) {
            float r = sr[j], m = si[j];
            sr[j] = fmaf(ph.x, r, -ph.y * m);
            si[j] = fmaf(ph.x, m, ph.y * r);
        }
    }

    // ---- <Z_0> = sum_k Re(psi_lo[k] * conj(psi_hi[k])) ----
    float ev = 0.f;
#pragma unroll
    for (int j = 0; j < 16; j++) {
        ev = fmaf(sr[j], sr[j + 16], ev);
        ev = fmaf(si[j], si[j + 16], ev);
    }
    out[p] = ev;
}

extern "C" void kernel_launch(void* const* d_in, const int* in_sizes, int n_in,
                              void* d_out, int out_size) {
    const float* x = nullptr;
    const float* thetas = nullptr;
    const float* phis = nullptr;
    for (int i = 0; i < n_in; i++) {
        if (in_sizes[i] == 12) thetas = (const float*)d_in[i];
        else if (in_sizes[i] == 3) phis = (const float*)d_in[i];
        else x = (const float*)d_in[i];
    }
    float* out = (float*)d_out;

    int P = out_size;
    int grid = (P + TPB - 1) / TPB;  // 432 for P = 262144
    sim_k<<<grid, TPB>>>(x, thetas, phis, out, P);
}